// round 14
// baseline (speedup 1.0000x reference)
#include <cuda_runtime.h>
#include <cuda_bf16.h>
#include <cstdint>
#include <math.h>

// ============================================================================
// Equiformer FFN, warp mma.sync m16n8k16 bf16 hi/lo 3-term split, fp32 acc.
// CTA = 64 nodes, 256 threads (8 warps 2m x 4n), 2 CTAs/SM (107KB smem).
// R14: P0 (h0) and P1 (out0) FUSED — scalar chunks stay in smem, out0
// accumulates across chunks in registers. P2/P3 = R9 structure (verbatim).
// X l>=1 slices pre-split by a vectorized prep; seg0 converted in-kernel.
// ============================================================================

#define THREADS 256
#define MAXCTA  1563

// ---- pre-split weights ----
#define OFF10 0        // [672 n][136]  (64n chunks: 10x8704 + 4352)
#define OFF11 91392    // [192 n][72]   (2 chunks of 96 n: 6912 each)
#define OFF12 105216   // [96 n][40]
#define OFF20 109056   // 12 blocks [kc*2+h][64 n][72]  (k64 chunks, n halves)
#define OFF21 164352   // 2 x [64 n][104]  (K chunks of 96)
#define OFF22 177664   // [32 n][104]
#define WTOT  180992
__device__ __align__(16) uint16_t g_wh[WTOT];
__device__ __align__(16) uint16_t g_wl[WTOT];

// ---- pre-split X (l>=1 only) per 64-node CTA ----
//  [8704 + i*4608)   X1_i [64 r][72]  i<3
//  [22528 + i*2560)  X2_i [64 r][40]  i<5
#define XBLK 35328
__device__ __align__(16) uint16_t g_xh[(size_t)MAXCTA * XBLK];
__device__ __align__(16) uint16_t g_xl[(size_t)MAXCTA * XBLK];

// gates fp32 [64 r][288]
__device__ __align__(16) float g_gate[(size_t)MAXCTA * 18432];

// ---- smem map (bytes) ----
// attr@0 | X A hi@512 lo@17920 [64x136] | W1_0 hi@35328 lo@52736 [64x136]
// scalar chunk hi@70144 lo@79360 [64x72] | W2_0 half hi@88576 lo@97792 [64x72]
#define SM_TOT 107008

__device__ __forceinline__ uint32_t s2u(const void* p) {
    uint32_t a;
    asm("{ .reg .u64 t; cvta.to.shared.u64 t, %1; cvt.u32.u64 %0, t; }" : "=r"(a) : "l"(p));
    return a;
}
__device__ __forceinline__ void ldm_x4(uint32_t d[4], uint32_t a) {
    asm volatile("ldmatrix.sync.aligned.m8n8.x4.shared.b16 {%0,%1,%2,%3}, [%4];"
                 : "=r"(d[0]), "=r"(d[1]), "=r"(d[2]), "=r"(d[3]) : "r"(a));
}
__device__ __forceinline__ void ldm_x2(uint32_t d[2], uint32_t a) {
    asm volatile("ldmatrix.sync.aligned.m8n8.x2.shared.b16 {%0,%1}, [%2];"
                 : "=r"(d[0]), "=r"(d[1]) : "r"(a));
}
__device__ __forceinline__ void mma_bf(float (&c)[4], const uint32_t (&a)[4],
                                       const uint32_t (&b)[2]) {
    asm volatile("mma.sync.aligned.m16n8k16.row.col.f32.bf16.bf16.f32 "
                 "{%0,%1,%2,%3},{%4,%5,%6,%7},{%8,%9},{%0,%1,%2,%3};"
                 : "+f"(c[0]), "+f"(c[1]), "+f"(c[2]), "+f"(c[3])
                 : "r"(a[0]), "r"(a[1]), "r"(a[2]), "r"(a[3]), "r"(b[0]), "r"(b[1]));
}
__device__ __forceinline__ void split(float v, uint16_t& h, uint16_t& l) {
    const __nv_bfloat16 hb = __float2bfloat16_rn(v);
    h = __bfloat16_as_ushort(hb);
    l = __bfloat16_as_ushort(__float2bfloat16_rn(v - __bfloat162float(hb)));
}
__device__ __forceinline__ void st_pair(uint16_t* bH, uint16_t* bL, int idx,
                                        float v0, float v1) {
    uint16_t h0, l0, h1, l1;
    split(v0, h0, l0);
    split(v1, h1, l1);
    *reinterpret_cast<uint32_t*>(bH + idx) = (uint32_t)h0 | ((uint32_t)h1 << 16);
    *reinterpret_cast<uint32_t*>(bL + idx) = (uint32_t)l0 | ((uint32_t)l1 << 16);
}
__device__ __forceinline__ void cp16(uint32_t dst, const void* src) {
    asm volatile("cp.async.cg.shared.global [%0], [%1], 16;" :: "r"(dst), "l"(src));
}
#define CP_COMMIT() asm volatile("cp.async.commit_group;" ::: "memory")
#define CP_WAIT0()  asm volatile("cp.async.wait_group 0;" ::: "memory")

__device__ __forceinline__ void cpy2(uint32_t dH, uint32_t dL,
                                     const uint16_t* sH, const uint16_t* sL, int elems) {
    const int n16 = elems >> 3;
    for (int i = threadIdx.x; i < n16; i += THREADS) {
        cp16(dH + i * 16, sH + i * 8);
        cp16(dL + i * 16, sL + i * 8);
    }
}

// ---- X seg0 conversion in-kernel (coalesced) ----
__device__ __forceinline__ void pack8(const float* v, uint32_t hi[4], uint32_t lo[4]) {
#pragma unroll
    for (int q = 0; q < 4; q++) {
        uint16_t h0, l0, h1, l1;
        split(v[2 * q], h0, l0);
        split(v[2 * q + 1], h1, l1);
        hi[q] = (uint32_t)h0 | ((uint32_t)h1 << 16);
        lo[q] = (uint32_t)l0 | ((uint32_t)l1 << 16);
    }
}
__device__ void conv_seg0(uint32_t dH, uint32_t dL, const float* __restrict__ X,
                          int nbase, int Nn) {
    for (int idx = threadIdx.x; idx < 1024; idx += THREADS) {
        const int r = idx >> 4, k8 = idx & 15;
        const float4* p = reinterpret_cast<const float4*>(
            X + (size_t)min(nbase + r, Nn - 1) * 480 + k8 * 8);
        const float4 a = __ldg(&p[0]), b = __ldg(&p[1]);
        const float v[8] = {a.x, a.y, a.z, a.w, b.x, b.y, b.z, b.w};
        uint32_t hi[4], lo[4];
        pack8(v, hi, lo);
        asm volatile("st.shared.v4.b32 [%0], {%1,%2,%3,%4};"
                     :: "r"(dH + r * 272 + k8 * 16), "r"(hi[0]), "r"(hi[1]),
                        "r"(hi[2]), "r"(hi[3]) : "memory");
        asm volatile("st.shared.v4.b32 [%0], {%1,%2,%3,%4};"
                     :: "r"(dL + r * 272 + k8 * 16), "r"(lo[0]), "r"(lo[1]),
                        "r"(lo[2]), "r"(lo[3]) : "memory");
    }
}

template <int NTW>
__device__ __forceinline__ void zacc(float (&acc)[2][NTW][4]) {
#pragma unroll
    for (int m = 0; m < 2; m++)
#pragma unroll
        for (int j = 0; j < NTW; j++)
#pragma unroll
            for (int q = 0; q < 4; q++) acc[m][j][q] = 0.0f;
}

template <int KT, int NTW>
__device__ __forceinline__ void mma_tile(uint32_t uAH, uint32_t uAL, uint32_t uBH,
                                         uint32_t uBL, int Kpad, int rowBase, int n8Base,
                                         int lane, float (&acc)[2][NTW][4]) {
    const int ar  = rowBase + (lane & 15);
    const int ak8 = (lane >> 4) * 8;
    const int bn  = lane & 7;
    const int bk8 = ((lane >> 3) & 1) * 8;
#pragma unroll 1
    for (int kt = 0; kt < KT; kt++) {
        const int kb = kt * 16;
        uint32_t Ah[2][4], Al[2][4];
#pragma unroll
        for (int m = 0; m < 2; m++) {
            const uint32_t off = (uint32_t)(((ar + m * 16) * Kpad + kb + ak8) * 2);
            ldm_x4(Ah[m], uAH + off);
            ldm_x4(Al[m], uAL + off);
        }
#pragma unroll
        for (int j = 0; j < NTW; j++) {
            const uint32_t boff =
                (uint32_t)((((n8Base + j) * 8 + bn) * Kpad + kb + bk8) * 2);
            uint32_t Bh[2], Bl[2];
            ldm_x2(Bh, uBH + boff);
            ldm_x2(Bl, uBL + boff);
#pragma unroll
            for (int m = 0; m < 2; m++) {
                mma_bf(acc[m][j], Ah[m], Bh);
                mma_bf(acc[m][j], Ah[m], Bl);
                mma_bf(acc[m][j], Al[m], Bh);
            }
        }
    }
}

// out0 accumulate variant: acc[2][4][4] with jbase (half select)
template <int KT>
__device__ __forceinline__ void mma_tileO(uint32_t uAH, uint32_t uAL, uint32_t uBH,
                                          uint32_t uBL, int Kpad, int rowBase,
                                          int n8Base, int lane,
                                          float (&acc)[2][4][4], int jbase) {
    const int ar  = rowBase + (lane & 15);
    const int ak8 = (lane >> 4) * 8;
    const int bn  = lane & 7;
    const int bk8 = ((lane >> 3) & 1) * 8;
#pragma unroll 1
    for (int kt = 0; kt < KT; kt++) {
        const int kb = kt * 16;
        uint32_t Ah[2][4], Al[2][4];
#pragma unroll
        for (int m = 0; m < 2; m++) {
            const uint32_t off = (uint32_t)(((ar + m * 16) * Kpad + kb + ak8) * 2);
            ldm_x4(Ah[m], uAH + off);
            ldm_x4(Al[m], uAL + off);
        }
#pragma unroll
        for (int j = 0; j < 2; j++) {
            const uint32_t boff =
                (uint32_t)((((n8Base + j) * 8 + bn) * Kpad + kb + bk8) * 2);
            uint32_t Bh[2], Bl[2];
            ldm_x2(Bh, uBH + boff);
            ldm_x2(Bl, uBL + boff);
#pragma unroll
            for (int m = 0; m < 2; m++) {
                mma_bf(acc[m][jbase + j], Ah[m], Bh);
                mma_bf(acc[m][jbase + j], Ah[m], Bl);
                mma_bf(acc[m][jbase + j], Al[m], Bh);
            }
        }
    }
}

// ---- prep1: weights ----
__device__ __forceinline__ void prep_w(const float* __restrict__ W, int K, int N,
                                       int Kpad, int base) {
    const int tot = K * N;
    for (int idx = blockIdx.x * blockDim.x + threadIdx.x; idx < tot;
         idx += gridDim.x * blockDim.x) {
        const int k = idx / N, n = idx - k * N;
        uint16_t h, l;
        split(__ldg(&W[idx]), h, l);
        g_wh[base + n * Kpad + k] = h;
        g_wl[base + n * Kpad + k] = l;
    }
}
__global__ void prep1(const float* W1_0, const float* W1_1, const float* W1_2,
                      const float* W2_0, const float* W2_1, const float* W2_2) {
    prep_w(W1_0, 128, 672, 136, OFF10);
    prep_w(W1_1, 64, 192, 72, OFF11);
    prep_w(W1_2, 32, 96, 40, OFF12);
    // W2_0: [kc k64][h n64] blocks of [64n][72]
    for (int idx = blockIdx.x * blockDim.x + threadIdx.x; idx < 384 * 128;
         idx += gridDim.x * blockDim.x) {
        const int k = idx / 128, n = idx - k * 128;
        const int kc = k >> 6, kk = k & 63, h2 = n >> 6, nl = n & 63;
        uint16_t h, l;
        split(__ldg(&W2_0[idx]), h, l);
        g_wh[OFF20 + (kc * 2 + h2) * 4608 + nl * 72 + kk] = h;
        g_wl[OFF20 + (kc * 2 + h2) * 4608 + nl * 72 + kk] = l;
    }
    for (int idx = blockIdx.x * blockDim.x + threadIdx.x; idx < 192 * 64;
         idx += gridDim.x * blockDim.x) {
        const int k = idx / 64, n = idx - k * 64;
        const int kc = k / 96, kk = k - kc * 96;
        uint16_t h, l;
        split(__ldg(&W2_1[idx]), h, l);
        g_wh[OFF21 + kc * 6656 + n * 104 + kk] = h;
        g_wl[OFF21 + kc * 6656 + n * 104 + kk] = l;
    }
    prep_w(W2_2, 96, 32, 104, OFF22);
}

// ---- prep2: X l>=1 slices -> hi/lo (vectorized 16B stores) ----
__global__ void prep2(const float* __restrict__ X, int Nn, int nct) {
    const int total = nct * 64 * 44;   // 24 X1 units + 20 X2 units per node
    for (int idx = blockIdx.x * blockDim.x + threadIdx.x; idx < total;
         idx += gridDim.x * blockDim.x) {
        const int node = idx / 44, u = idx - node * 44;
        const int r = node & 63, cta = node >> 6;
        const float* p = X + (size_t)min(node, Nn - 1) * 480;
        const size_t base = (size_t)cta * XBLK;
        float v[8];
        size_t off;
        if (u < 24) {
            const int i = u >> 3, b = u & 7;
#pragma unroll
            for (int q = 0; q < 8; q++) v[q] = __ldg(&p[128 + 24 * b + i + 3 * q]);
            off = base + 8704 + i * 4608 + r * 72 + b * 8;
        } else {
            const int uu = u - 24, i = uu >> 2, b = uu & 3;
#pragma unroll
            for (int q = 0; q < 8; q++) v[q] = __ldg(&p[320 + 40 * b + i + 5 * q]);
            off = base + 22528 + i * 2560 + r * 40 + b * 8;
        }
        uint32_t hi[4], lo[4];
        pack8(v, hi, lo);
        *reinterpret_cast<uint4*>(g_xh + off) = make_uint4(hi[0], hi[1], hi[2], hi[3]);
        *reinterpret_cast<uint4*>(g_xl + off) = make_uint4(lo[0], lo[1], lo[2], lo[3]);
    }
}

__global__ void __launch_bounds__(THREADS, 2)
ffn_main(const float* __restrict__ X, const float* __restrict__ attr,
         const float* __restrict__ b1, const float* __restrict__ b2,
         float* __restrict__ out, int Nn) {
    extern __shared__ char smem[];
    float* sAttr = (float*)smem;
    const uint32_t sb = s2u(smem);
    const int tid = threadIdx.x, lane = tid & 31, w = tid >> 5;
    const int g = lane >> 2, t2 = lane & 3;
    const int mt = w >> 2, nt = w & 3;   // 2m x 4n
    const size_t cta = blockIdx.x;
    const int nbase = (int)cta * 64;
    const uint16_t* xh = g_xh + cta * XBLK;
    const uint16_t* xl = g_xl + cta * XBLK;
    float* gate = g_gate + cta * 18432;
    uint16_t* scH = (uint16_t*)(smem + 70144);
    uint16_t* scL = (uint16_t*)(smem + 79360);

    const float I10 = 0.08838834764831843f, I11 = 0.125f, I12 = 0.17677669529663687f;
    const float I20 = 0.05103103630798288f, I21 = 0.07216878364870323f,
                I22 = 0.10206207261596577f;

    // ===== P0+P1 fused: h0 chunks (64 cols) + out0 partial-K accumulation =====
    cpy2(sb + 35328, sb + 52736, g_wh + OFF10, g_wl + OFF10, 8704);
    CP_COMMIT();
    if (tid < 64) sAttr[tid] = attr[min(nbase + tid, Nn - 1)];
    conv_seg0(sb + 512, sb + 17920, X, nbase, Nn);

    float accO[2][4][4];
    zacc<4>(accO);

    for (int ch = 0; ch < 11; ch++) {
        CP_WAIT0();
        __syncthreads();
        if (ch < 10) {
            float acc[2][2][4];
            zacc<2>(acc);
            mma_tile<8, 2>(sb + 512, sb + 17920, sb + 35328, sb + 52736, 136,
                           mt * 32, nt * 2, lane, acc);
            __syncthreads();
            // prefetch next W1_0 chunk (+ W2_0 half0 if scalar chunk)
            if (ch < 9)
                cpy2(sb + 35328, sb + 52736, g_wh + OFF10 + (ch + 1) * 8704,
                     g_wl + OFF10 + (ch + 1) * 8704, 8704);
            else
                cpy2(sb + 35328, sb + 52736, g_wh + OFF10 + 87040,
                     g_wl + OFF10 + 87040, 4352);
            if (ch < 6)
                cpy2(sb + 88576, sb + 97792, g_wh + OFF20 + (ch * 2) * 4608,
                     g_wl + OFF20 + (ch * 2) * 4608, 4608);
            CP_COMMIT();
            // epilogue
#pragma unroll
            for (int m = 0; m < 2; m++) {
                const int r0 = mt * 32 + m * 16 + g;
#pragma unroll
                for (int j = 0; j < 2; j++) {
                    const int cl = (nt * 2 + j) * 8 + t2 * 2;
                    const int gc = ch * 64 + cl;
                    const float bb0 = __ldg(&b1[gc]), bb1 = __ldg(&b1[gc + 1]);
#pragma unroll
                    for (int h2 = 0; h2 < 2; h2++) {
                        const int r = r0 + h2 * 8;
                        const float a = sAttr[r] * I10;
                        const float x0 = acc[m][j][h2 * 2] * a + bb0;
                        const float x1 = acc[m][j][h2 * 2 + 1] * a + bb1;
                        const float s0 = 1.0f / (1.0f + __expf(-x0));
                        const float s1 = 1.0f / (1.0f + __expf(-x1));
                        if (ch < 6)
                            st_pair(scH, scL, r * 72 + cl, x0 * s0, x1 * s1);
                        else
                            *reinterpret_cast<float2*>(gate + r * 288 + gc - 384) =
                                make_float2(s0, s1);
                    }
                }
            }
            if (ch < 6) {
                // out0 partial: half 0
                CP_WAIT0();
                __syncthreads();
                mma_tileO<4>(sb + 70144, sb + 79360, sb + 88576, sb + 97792, 72,
                             mt * 32, nt * 2, lane, accO, 0);
                __syncthreads();
                cpy2(sb + 88576, sb + 97792, g_wh + OFF20 + (ch * 2 + 1) * 4608,
                     g_wl + OFF20 + (ch * 2 + 1) * 4608, 4608);
                CP_COMMIT();
                CP_WAIT0();
                __syncthreads();
                mma_tileO<4>(sb + 70144, sb + 79360, sb + 88576, sb + 97792, 72,
                             mt * 32, nt * 2, lane, accO, 2);
            }
        } else {   // tail chunk: 32 cols, gates only
            float acc[2][1][4];
            zacc<1>(acc);
            mma_tile<8, 1>(sb + 512, sb + 17920, sb + 35328, sb + 52736, 136,
                           mt * 32, nt, lane, acc);
            __syncthreads();
#pragma unroll
            for (int m = 0; m < 2; m++) {
                const int r0 = mt * 32 + m * 16 + g;
                const int gc = 640 + nt * 8 + t2 * 2;
                const float bb0 = __ldg(&b1[gc]), bb1 = __ldg(&b1[gc + 1]);
#pragma unroll
                for (int h2 = 0; h2 < 2; h2++) {
                    const int r = r0 + h2 * 8;
                    const float a = sAttr[r] * I10;
                    const float x0 = acc[m][0][h2 * 2] * a + bb0;
                    const float x1 = acc[m][0][h2 * 2 + 1] * a + bb1;
                    *reinterpret_cast<float2*>(gate + r * 288 + gc - 384) =
                        make_float2(1.0f / (1.0f + __expf(-x0)),
                                    1.0f / (1.0f + __expf(-x1)));
                }
            }
        }
    }
    __syncthreads();
    // P2 first inputs: X1_0 + W1_1 chunk0 (A/X buffers dead now)
    cpy2(sb + 512, sb + 9728, xh + 8704, xl + 8704, 4608);
    cpy2(sb + 18944, sb + 32768, g_wh + OFF11, g_wl + OFF11, 6912);
    CP_COMMIT();
    // out0 epilogue (overlaps copy)
#pragma unroll
    for (int m = 0; m < 2; m++) {
        const int r0 = mt * 32 + m * 16 + g;
#pragma unroll
        for (int jj = 0; jj < 4; jj++) {
            const int c = (jj >> 1) * 64 + (nt * 2 + (jj & 1)) * 8 + t2 * 2;
            const float bb0 = __ldg(&b2[c]), bb1 = __ldg(&b2[c + 1]);
#pragma unroll
            for (int h2 = 0; h2 < 2; h2++) {
                const int r = r0 + h2 * 8, node = nbase + r;
                if (node < Nn) {
                    const float a = sAttr[r] * I20;
                    *reinterpret_cast<float2*>(out + (size_t)node * 480 + c) =
                        make_float2(accO[m][jj][h2 * 2] * a + bb0,
                                    accO[m][jj][h2 * 2 + 1] * a + bb1);
                }
            }
        }
    }

    // ===== P2: mid1_i -> out1_i fused, K-split 96+96 (i=0..2) — R9 verbatim =====
    {
        uint16_t* mH = (uint16_t*)(smem + 46592);
        uint16_t* mL = (uint16_t*)(smem + 59904);
        for (int i = 0; i < 3; i++) {
            float acc2[2][2][4];
            zacc<2>(acc2);
            for (int kc = 0; kc < 2; kc++) {
                CP_WAIT0();
                __syncthreads();
                float acc[2][3][4];
                zacc<3>(acc);
                mma_tile<4, 3>(sb + 512, sb + 9728, sb + 18944, sb + 32768, 72,
                               mt * 32, nt * 3, lane, acc);
                __syncthreads();
                cpy2(sb + 73216, sb + 86528, g_wh + OFF21 + kc * 6656,
                     g_wl + OFF21 + kc * 6656, 6656);
                CP_COMMIT();
                if (kc == 0) {
                    cpy2(sb + 18944, sb + 32768, g_wh + OFF11 + 6912,
                         g_wl + OFF11 + 6912, 6912);
                } else if (i < 2) {
                    cpy2(sb + 18944, sb + 32768, g_wh + OFF11, g_wl + OFF11, 6912);
                    cpy2(sb + 512, sb + 9728, xh + 8704 + (i + 1) * 4608,
                         xl + 8704 + (i + 1) * 4608, 4608);
                } else {
                    cpy2(sb + 512, sb + 5632, xh + 22528, xl + 22528, 2560);
                    cpy2(sb + 10752, sb + 18432, g_wh + OFF12, g_wl + OFF12, 3840);
                    cpy2(sb + 26112, sb + 32768, g_wh + OFF22, g_wl + OFF22, 3328);
                }
                CP_COMMIT();
#pragma unroll
                for (int m = 0; m < 2; m++) {
                    const int r0 = mt * 32 + m * 16 + g;
#pragma unroll
                    for (int j = 0; j < 3; j++) {
                        const int c = (nt * 3 + j) * 8 + t2 * 2;
#pragma unroll
                        for (int h2 = 0; h2 < 2; h2++) {
                            const int r = r0 + h2 * 8;
                            const float a = sAttr[r] * I11;
                            const float2 gg = *reinterpret_cast<const float2*>(
                                gate + r * 288 + kc * 96 + c);
                            st_pair(mH, mL, r * 104 + c,
                                    acc[m][j][h2 * 2] * a * gg.x,
                                    acc[m][j][h2 * 2 + 1] * a * gg.y);
                        }
                    }
                }
                __syncthreads();
                asm volatile("cp.async.wait_group 1;" ::: "memory");
                __syncthreads();
                mma_tile<6, 2>(sb + 46592, sb + 59904, sb + 73216, sb + 86528, 104,
                               mt * 32, nt * 2, lane, acc2);
                __syncthreads();
            }
#pragma unroll
            for (int m = 0; m < 2; m++) {
                const int r0 = mt * 32 + m * 16 + g;
#pragma unroll
                for (int j = 0; j < 2; j++) {
                    const int c = (nt * 2 + j) * 8 + t2 * 2;
#pragma unroll
                    for (int h2 = 0; h2 < 2; h2++) {
                        const int r = r0 + h2 * 8, node = nbase + r;
                        if (node < Nn) {
                            const float a = sAttr[r] * I21;
                            out[(size_t)node * 480 + 128 + c * 3 + i] =
                                acc2[m][j][h2 * 2] * a;
                            out[(size_t)node * 480 + 128 + (c + 1) * 3 + i] =
                                acc2[m][j][h2 * 2 + 1] * a;
                        }
                    }
                }
            }
        }
    }

    // ===== P3: mid2_i -> out2_i fused (i=0..4) — R9 verbatim =====
    {
        uint16_t* mH = (uint16_t*)(smem + 46592);
        uint16_t* mL = (uint16_t*)(smem + 59904);
        for (int i = 0; i < 5; i++) {
            CP_WAIT0();
            __syncthreads();
            float acc[2][3][4];
            zacc<3>(acc);
            mma_tile<2, 3>(sb + 512, sb + 5632, sb + 10752, sb + 18432, 40,
                           mt * 32, nt * 3, lane, acc);
            __syncthreads();
            if (i < 4) {
                cpy2(sb + 512, sb + 5632, xh + 22528 + (i + 1) * 2560,
                     xl + 22528 + (i + 1) * 2560, 2560);
                CP_COMMIT();
            }
#pragma unroll
            for (int m = 0; m < 2; m++) {
                const int r0 = mt * 32 + m * 16 + g;
#pragma unroll
                for (int j = 0; j < 3; j++) {
                    const int c = (nt * 3 + j) * 8 + t2 * 2;
#pragma unroll
                    for (int h2 = 0; h2 < 2; h2++) {
                        const int r = r0 + h2 * 8;
                        const float a = sAttr[r] * I12;
                        const float2 gg = *reinterpret_cast<const float2*>(
                            gate + r * 288 + 192 + c);
                        st_pair(mH, mL, r * 104 + c, acc[m][j][h2 * 2] * a * gg.x,
                                acc[m][j][h2 * 2 + 1] * a * gg.y);
                    }
                }
            }
            __syncthreads();
            float acc2[2][1][4];
            zacc<1>(acc2);
            mma_tile<6, 1>(sb + 46592, sb + 59904, sb + 26112, sb + 32768, 104,
                           mt * 32, nt, lane, acc2);
            __syncthreads();
#pragma unroll
            for (int m = 0; m < 2; m++) {
                const int r0 = mt * 32 + m * 16 + g;
                const int c = nt * 8 + t2 * 2;
#pragma unroll
                for (int h2 = 0; h2 < 2; h2++) {
                    const int r = r0 + h2 * 8, node = nbase + r;
                    if (node < Nn) {
                        const float a = sAttr[r] * I22;
                        out[(size_t)node * 480 + 320 + c * 5 + i] =
                            acc2[m][0][h2 * 2] * a;
                        out[(size_t)node * 480 + 320 + (c + 1) * 5 + i] =
                            acc2[m][0][h2 * 2 + 1] * a;
                    }
                }
            }
        }
    }
}

extern "C" void kernel_launch(void* const* d_in, const int* in_sizes, int n_in,
                              void* d_out, int out_size) {
    const float* X    = (const float*)d_in[0];
    const float* attr = (const float*)d_in[1];
    const float* W1_0 = (const float*)d_in[2];
    const float* W1_1 = (const float*)d_in[3];
    const float* W1_2 = (const float*)d_in[4];
    const float* b1   = (const float*)d_in[5];
    const float* W2_0 = (const float*)d_in[6];
    const float* W2_1 = (const float*)d_in[7];
    const float* W2_2 = (const float*)d_in[8];
    const float* b2   = (const float*)d_in[9];
    float* out = (float*)d_out;

    const int N = in_sizes[0] / 480;
    int nct = (N + 63) / 64;
    if (nct > MAXCTA) nct = MAXCTA;

    prep1<<<160, 256>>>(W1_0, W1_1, W1_2, W2_0, W2_1, W2_2);
    prep2<<<2048, 256>>>(X, N, nct);
    cudaFuncSetAttribute(ffn_main, cudaFuncAttributeMaxDynamicSharedMemorySize, SM_TOT);
    ffn_main<<<nct, THREADS, SM_TOT>>>(X, attr, b1, b2, out, N);
}

// round 15
// speedup vs baseline: 1.2530x; 1.2530x over previous
#include <cuda_runtime.h>
#include <cuda_fp16.h>
#include <cstdint>
#include <math.h>

// ============================================================================
// Equiformer FFN via mma.sync m16n8k16 fp16, 2-term scheme:
//   activations A = fp16 (single), weights B = fp16 hi + fp16 lo,
//   D = A*Bh + A*Bl (fp16 products exact in fp32) -> rel_err ~2-4e-4.
// CTA = 64 nodes, 256 threads (8 warps 2m x 4n), 2 CTAs/SM. R9 phase/wait
// structure. X pre-split to fp16 by vectorized prep; weights by tiny prep.
// ============================================================================

#define THREADS 256
#define MAXCTA  1563

// ---- pre-split weights (fp16 hi/lo) ----
#define OFF10 0        // [672 n][136]   (7 chunks of 96 n, 13056 each)
#define OFF11 91392    // [192 n][72]    (2 chunks of 96 n, 6912 each)
#define OFF12 105216   // [96 n][40]
#define OFF20 109056   // 8 x [128 n][56]   (K chunks of 48)
#define OFF21 166400   // 2 x [64 n][104]   (K chunks of 96)
#define OFF22 179712   // [32 n][104]
#define WTOT  183040
__device__ __align__(16) uint16_t g_wh[WTOT];
__device__ __align__(16) uint16_t g_wl[WTOT];

// ---- pre-converted X (fp16 single) per 64-node CTA ----
//  [0)            seg0 [64 r][136]
//  [8704+i*4608)  X1_i [64 r][72]   i<3
//  [22528+i*2560) X2_i [64 r][40]   i<5
#define XBLK 35328
__device__ __align__(16) uint16_t g_x[(size_t)MAXCTA * XBLK];

// scalars fp16 [64 r][392] + gates fp32 [64 r][288]
__device__ __align__(16) uint16_t g_sc[(size_t)MAXCTA * 25088];
__device__ __align__(16) float    g_gate[(size_t)MAXCTA * 18432];

#define SM_TOT 77824

__device__ __forceinline__ uint32_t s2u(const void* p) {
    uint32_t a;
    asm("{ .reg .u64 t; cvta.to.shared.u64 t, %1; cvt.u32.u64 %0, t; }" : "=r"(a) : "l"(p));
    return a;
}
__device__ __forceinline__ void ldm_x4(uint32_t d[4], uint32_t a) {
    asm volatile("ldmatrix.sync.aligned.m8n8.x4.shared.b16 {%0,%1,%2,%3}, [%4];"
                 : "=r"(d[0]), "=r"(d[1]), "=r"(d[2]), "=r"(d[3]) : "r"(a));
}
__device__ __forceinline__ void ldm_x2(uint32_t d[2], uint32_t a) {
    asm volatile("ldmatrix.sync.aligned.m8n8.x2.shared.b16 {%0,%1}, [%2];"
                 : "=r"(d[0]), "=r"(d[1]) : "r"(a));
}
__device__ __forceinline__ void mma_f16(float (&c)[4], const uint32_t (&a)[4],
                                        const uint32_t (&b)[2]) {
    asm volatile("mma.sync.aligned.m16n8k16.row.col.f32.f16.f16.f32 "
                 "{%0,%1,%2,%3},{%4,%5,%6,%7},{%8,%9},{%0,%1,%2,%3};"
                 : "+f"(c[0]), "+f"(c[1]), "+f"(c[2]), "+f"(c[3])
                 : "r"(a[0]), "r"(a[1]), "r"(a[2]), "r"(a[3]), "r"(b[0]), "r"(b[1]));
}
__device__ __forceinline__ void split16(float v, uint16_t& h, uint16_t& l) {
    const __half hb = __float2half_rn(v);
    h = __half_as_ushort(hb);
    l = __half_as_ushort(__float2half_rn(v - __half2float(hb)));
}
__device__ __forceinline__ uint32_t pk16(float v0, float v1) {
    return (uint32_t)__half_as_ushort(__float2half_rn(v0)) |
           ((uint32_t)__half_as_ushort(__float2half_rn(v1)) << 16);
}
__device__ __forceinline__ void cp16(uint32_t dst, const void* src) {
    asm volatile("cp.async.cg.shared.global [%0], [%1], 16;" :: "r"(dst), "l"(src));
}
#define CP_COMMIT() asm volatile("cp.async.commit_group;" ::: "memory")
#define CP_WAIT0()  asm volatile("cp.async.wait_group 0;" ::: "memory")
#define CP_WAIT1()  asm volatile("cp.async.wait_group 1;" ::: "memory")

__device__ __forceinline__ void cpy1(uint32_t d, const uint16_t* s, int elems) {
    const int n16 = elems >> 3;
    for (int i = threadIdx.x; i < n16; i += THREADS) cp16(d + i * 16, s + i * 8);
}
__device__ __forceinline__ void cpy2(uint32_t dH, uint32_t dL,
                                     const uint16_t* sH, const uint16_t* sL, int elems) {
    const int n16 = elems >> 3;
    for (int i = threadIdx.x; i < n16; i += THREADS) {
        cp16(dH + i * 16, sH + i * 8);
        cp16(dL + i * 16, sL + i * 8);
    }
}
// scalars: 64 rows x 6 chunks of 16B from [r][392] col kcOff -> [r][56pad]
__device__ __forceinline__ void cpy_sc48(uint32_t d, const uint16_t* s, int kcOff) {
    for (int i = threadIdx.x; i < 384; i += THREADS) {
        const int r = i / 6, ch = i - r * 6;
        cp16(d + r * 112 + ch * 16, s + r * 392 + kcOff + ch * 8);
    }
}

template <int NTW>
__device__ __forceinline__ void zacc(float (&acc)[2][NTW][4]) {
#pragma unroll
    for (int m = 0; m < 2; m++)
#pragma unroll
        for (int j = 0; j < NTW; j++)
#pragma unroll
            for (int q = 0; q < 4; q++) acc[m][j][q] = 0.0f;
}

// 2-term mma: A single (uA), B hi/lo (uBH,uBL). Same Kpad for A and B.
template <int KT, int NTW>
__device__ __forceinline__ void mma2(uint32_t uA, uint32_t uBH, uint32_t uBL,
                                     int Kpad, int rowBase, int n8Base,
                                     int lane, float (&acc)[2][NTW][4]) {
    const int ar  = rowBase + (lane & 15);
    const int ak8 = (lane >> 4) * 8;
    const int bn  = lane & 7;
    const int bk8 = ((lane >> 3) & 1) * 8;
#pragma unroll 1
    for (int kt = 0; kt < KT; kt++) {
        const int kb = kt * 16;
        uint32_t A[2][4];
#pragma unroll
        for (int m = 0; m < 2; m++)
            ldm_x4(A[m], uA + (uint32_t)(((ar + m * 16) * Kpad + kb + ak8) * 2));
#pragma unroll
        for (int j = 0; j < NTW; j++) {
            const uint32_t boff =
                (uint32_t)((((n8Base + j) * 8 + bn) * Kpad + kb + bk8) * 2);
            uint32_t Bh[2], Bl[2];
            ldm_x2(Bh, uBH + boff);
            ldm_x2(Bl, uBL + boff);
#pragma unroll
            for (int m = 0; m < 2; m++) {
                mma_f16(acc[m][j], A[m], Bh);
                mma_f16(acc[m][j], A[m], Bl);
            }
        }
    }
}

// ---- prep1: weights -> fp16 hi/lo ----
__device__ __forceinline__ void prep_w(const float* __restrict__ W, int K, int N,
                                       int Kpad, int base) {
    const int tot = K * N;
    for (int idx = blockIdx.x * blockDim.x + threadIdx.x; idx < tot;
         idx += gridDim.x * blockDim.x) {
        const int k = idx / N, n = idx - k * N;
        uint16_t h, l;
        split16(__ldg(&W[idx]), h, l);
        g_wh[base + n * Kpad + k] = h;
        g_wl[base + n * Kpad + k] = l;
    }
}
__global__ void prep1(const float* W1_0, const float* W1_1, const float* W1_2,
                      const float* W2_0, const float* W2_1, const float* W2_2) {
    prep_w(W1_0, 128, 672, 136, OFF10);
    prep_w(W1_1, 64, 192, 72, OFF11);
    prep_w(W1_2, 32, 96, 40, OFF12);
    for (int idx = blockIdx.x * blockDim.x + threadIdx.x; idx < 384 * 128;
         idx += gridDim.x * blockDim.x) {
        const int k = idx / 128, n = idx - k * 128;
        const int kc = k / 48, kk = k - kc * 48;
        uint16_t h, l;
        split16(__ldg(&W2_0[idx]), h, l);
        g_wh[OFF20 + kc * 7168 + n * 56 + kk] = h;
        g_wl[OFF20 + kc * 7168 + n * 56 + kk] = l;
    }
    for (int idx = blockIdx.x * blockDim.x + threadIdx.x; idx < 192 * 64;
         idx += gridDim.x * blockDim.x) {
        const int k = idx / 64, n = idx - k * 64;
        const int kc = k / 96, kk = k - kc * 96;
        uint16_t h, l;
        split16(__ldg(&W2_1[idx]), h, l);
        g_wh[OFF21 + kc * 6656 + n * 104 + kk] = h;
        g_wl[OFF21 + kc * 6656 + n * 104 + kk] = l;
    }
    prep_w(W2_2, 96, 32, 104, OFF22);
}

// ---- prep2: X -> fp16 single, vectorized 16B stores (60 units/node) ----
__global__ void prep2(const float* __restrict__ X, int Nn, int nct) {
    const int total = nct * 64 * 60;
    for (int idx = blockIdx.x * blockDim.x + threadIdx.x; idx < total;
         idx += gridDim.x * blockDim.x) {
        const int node = idx / 60, u = idx - node * 60;
        const int r = node & 63, cta = node >> 6;
        const float* p = X + (size_t)min(node, Nn - 1) * 480;
        const size_t base = (size_t)cta * XBLK;
        float v[8];
        size_t off;
        if (u < 16) {                       // seg0 contiguous
#pragma unroll
            for (int q = 0; q < 8; q++) v[q] = __ldg(&p[u * 8 + q]);
            off = base + r * 136 + u * 8;
        } else if (u < 40) {                // X1 component i, stride 3
            const int i = (u - 16) >> 3, b = (u - 16) & 7;
#pragma unroll
            for (int q = 0; q < 8; q++) v[q] = __ldg(&p[128 + 24 * b + i + 3 * q]);
            off = base + 8704 + i * 4608 + r * 72 + b * 8;
        } else {                            // X2 component i, stride 5
            const int i = (u - 40) >> 2, b = (u - 40) & 3;
#pragma unroll
            for (int q = 0; q < 8; q++) v[q] = __ldg(&p[320 + 40 * b + i + 5 * q]);
            off = base + 22528 + i * 2560 + r * 40 + b * 8;
        }
        uint4 o;
        o.x = pk16(v[0], v[1]);
        o.y = pk16(v[2], v[3]);
        o.z = pk16(v[4], v[5]);
        o.w = pk16(v[6], v[7]);
        *reinterpret_cast<uint4*>(g_x + off) = o;
    }
}

__global__ void __launch_bounds__(THREADS, 2)
ffn_main(const float* __restrict__ attr, const float* __restrict__ b1,
         const float* __restrict__ b2, float* __restrict__ out, int Nn) {
    extern __shared__ char smem[];
    float* sAttr = (float*)smem;
    const uint32_t sb = s2u(smem);
    const int tid = threadIdx.x, lane = tid & 31, w = tid >> 5;
    const int g = lane >> 2, t2 = lane & 3;
    const int mt = w >> 2, nt = w & 3;   // 2m x 4n
    const size_t cta = blockIdx.x;
    const int nbase = (int)cta * 64;
    const uint16_t* x = g_x + cta * XBLK;
    uint16_t* sc = g_sc + cta * 25088;
    float* gate = g_gate + cta * 18432;

    const float I10 = 0.08838834764831843f, I11 = 0.125f, I12 = 0.17677669529663687f;
    const float I20 = 0.05103103630798288f, I21 = 0.07216878364870323f,
                I22 = 0.10206207261596577f;

    // ===== P0: h0 = x0 @ W1_0 (7 N-chunks of 96) =====
    // A seg0 @512 (17408B); B chunk hi@17920 lo@44032 (26112B each)
    cpy1(sb + 512, x, 8704);
    cpy2(sb + 17920, sb + 44032, g_wh + OFF10, g_wl + OFF10, 13056);
    CP_COMMIT();
    if (tid < 64) sAttr[tid] = attr[min(nbase + tid, Nn - 1)];
    for (int ch = 0; ch < 7; ch++) {
        CP_WAIT0();
        __syncthreads();
        float acc[2][3][4];
        zacc<3>(acc);
        mma2<8, 3>(sb + 512, sb + 17920, sb + 44032, 136, mt * 32, nt * 3, lane, acc);
        __syncthreads();
        if (ch < 6) {
            cpy2(sb + 17920, sb + 44032, g_wh + OFF10 + (ch + 1) * 13056,
                 g_wl + OFF10 + (ch + 1) * 13056, 13056);
            CP_COMMIT();
        } else {
            // prefetch P1 kc0: A scalars cols 0..47 @512, B W2_0 kc0 @14848/29184
            cpy_sc48(sb + 512, sc, 0);
            cpy2(sb + 14848, sb + 29184, g_wh + OFF20, g_wl + OFF20, 7168);
            CP_COMMIT();
        }
#pragma unroll
        for (int m = 0; m < 2; m++) {
            const int r0 = mt * 32 + m * 16 + g;
#pragma unroll
            for (int j = 0; j < 3; j++) {
                const int gc = ch * 96 + (nt * 3 + j) * 8 + t2 * 2;
                const float bb0 = __ldg(&b1[gc]), bb1 = __ldg(&b1[gc + 1]);
#pragma unroll
                for (int h2 = 0; h2 < 2; h2++) {
                    const int r = r0 + h2 * 8;
                    const float a = sAttr[r] * I10;
                    const float x0 = acc[m][j][h2 * 2] * a + bb0;
                    const float x1 = acc[m][j][h2 * 2 + 1] * a + bb1;
                    const float s0 = 1.0f / (1.0f + __expf(-x0));
                    const float s1 = 1.0f / (1.0f + __expf(-x1));
                    if (gc < 384)
                        *reinterpret_cast<uint32_t*>(sc + r * 392 + gc) =
                            pk16(x0 * s0, x1 * s1);
                    else
                        *reinterpret_cast<float2*>(gate + r * 288 + gc - 384) =
                            make_float2(s0, s1);
                }
            }
        }
    }

    // ===== P1: out0 = scalars @ W2_0 (8 K-chunks of 48, double-buffered) =====
    // A chunks [64][56] @512/7680; B [128][56] hi/lo: b0 @14848/29184, b1 @43520/57856
    {
        const uint32_t aB[2] = {sb + 512, sb + 7680};
        const uint32_t bH[2] = {sb + 14848, sb + 43520};
        const uint32_t bL[2] = {sb + 29184, sb + 57856};
        float acc[2][4][4];
        zacc<4>(acc);
        for (int kc = 0; kc < 8; kc++) {
            const int s = kc & 1;
            if (kc < 7) {
                cpy_sc48(aB[1 - s], sc, (kc + 1) * 48);
                cpy2(bH[1 - s], bL[1 - s], g_wh + OFF20 + (kc + 1) * 7168,
                     g_wl + OFF20 + (kc + 1) * 7168, 7168);
                CP_COMMIT();
                CP_WAIT1();
            } else {
                CP_WAIT0();
            }
            __syncthreads();
            mma2<3, 4>(aB[s], bH[s], bL[s], 56, mt * 32, nt * 4, lane, acc);
            __syncthreads();
        }
        // prefetch P2: X1_0 @512, W1_1 chunk0 hi@9728 lo@23552
        cpy1(sb + 512, x + 8704, 4608);
        cpy2(sb + 9728, sb + 23552, g_wh + OFF11, g_wl + OFF11, 6912);
        CP_COMMIT();
        // out0 epilogue
#pragma unroll
        for (int m = 0; m < 2; m++) {
            const int r0 = mt * 32 + m * 16 + g;
#pragma unroll
            for (int j = 0; j < 4; j++) {
                const int c = (nt * 4 + j) * 8 + t2 * 2;
                const float bb0 = __ldg(&b2[c]), bb1 = __ldg(&b2[c + 1]);
#pragma unroll
                for (int h2 = 0; h2 < 2; h2++) {
                    const int r = r0 + h2 * 8, node = nbase + r;
                    if (node < Nn) {
                        const float a = sAttr[r] * I20;
                        *reinterpret_cast<float2*>(out + (size_t)node * 480 + c) =
                            make_float2(acc[m][j][h2 * 2] * a + bb0,
                                        acc[m][j][h2 * 2 + 1] * a + bb1);
                    }
                }
            }
        }
    }

    // ===== P2: mid1_i -> out1_i fused, K-split 96+96 (i=0..2) =====
    // X1 @512 (9216B); W1_1 hi@9728 lo@23552 (13824B each);
    // mid @37376 (13312B); W2_1 hi@50688 lo@64000 (13312B each)
    {
        uint16_t* mB = (uint16_t*)(smem + 37376);
        for (int i = 0; i < 3; i++) {
            float acc2[2][2][4];
            zacc<2>(acc2);
            for (int kc = 0; kc < 2; kc++) {
                CP_WAIT0();
                __syncthreads();
                float acc[2][3][4];
                zacc<3>(acc);
                mma2<4, 3>(sb + 512, sb + 9728, sb + 23552, 72, mt * 32,
                           nt * 3, lane, acc);
                __syncthreads();
                // group A: W2_1(kc)
                cpy2(sb + 50688, sb + 64000, g_wh + OFF21 + kc * 6656,
                     g_wl + OFF21 + kc * 6656, 6656);
                CP_COMMIT();
                // group B: next inputs
                if (kc == 0) {
                    cpy2(sb + 9728, sb + 23552, g_wh + OFF11 + 6912,
                         g_wl + OFF11 + 6912, 6912);
                } else if (i < 2) {
                    cpy2(sb + 9728, sb + 23552, g_wh + OFF11, g_wl + OFF11, 6912);
                    cpy1(sb + 512, x + 8704 + (i + 1) * 4608, 4608);
                } else {
                    // P3 preload: X2_0 @512, W1_2 hi@5632 lo@13312,
                    //             W2_2 hi@20992 lo@27648 (all dead regions)
                    cpy1(sb + 512, x + 22528, 2560);
                    cpy2(sb + 5632, sb + 13312, g_wh + OFF12, g_wl + OFF12, 3840);
                    cpy2(sb + 20992, sb + 27648, g_wh + OFF22, g_wl + OFF22, 3328);
                }
                CP_COMMIT();
                // mid epilogue -> smem (fp16 single)
#pragma unroll
                for (int m = 0; m < 2; m++) {
                    const int r0 = mt * 32 + m * 16 + g;
#pragma unroll
                    for (int j = 0; j < 3; j++) {
                        const int c = (nt * 3 + j) * 8 + t2 * 2;
#pragma unroll
                        for (int h2 = 0; h2 < 2; h2++) {
                            const int r = r0 + h2 * 8;
                            const float a = sAttr[r] * I11;
                            const float2 gg = *reinterpret_cast<const float2*>(
                                gate + r * 288 + kc * 96 + c);
                            *reinterpret_cast<uint32_t*>(mB + r * 104 + c) =
                                pk16(acc[m][j][h2 * 2] * a * gg.x,
                                     acc[m][j][h2 * 2 + 1] * a * gg.y);
                        }
                    }
                }
                __syncthreads();
                CP_WAIT1();   // W2_1(kc) landed; group B may pend
                __syncthreads();
                mma2<6, 2>(sb + 37376, sb + 50688, sb + 64000, 104, mt * 32,
                           nt * 2, lane, acc2);
                __syncthreads();
            }
            // out1 epilogue
#pragma unroll
            for (int m = 0; m < 2; m++) {
                const int r0 = mt * 32 + m * 16 + g;
#pragma unroll
                for (int j = 0; j < 2; j++) {
                    const int c = (nt * 2 + j) * 8 + t2 * 2;
#pragma unroll
                    for (int h2 = 0; h2 < 2; h2++) {
                        const int r = r0 + h2 * 8, node = nbase + r;
                        if (node < Nn) {
                            const float a = sAttr[r] * I21;
                            out[(size_t)node * 480 + 128 + c * 3 + i] =
                                acc2[m][j][h2 * 2] * a;
                            out[(size_t)node * 480 + 128 + (c + 1) * 3 + i] =
                                acc2[m][j][h2 * 2 + 1] * a;
                        }
                    }
                }
            }
        }
    }

    // ===== P3: mid2_i -> out2_i fused (i=0..4) =====
    // X2 @512 (5120B); W1_2 hi@5632 lo@13312; W2_2 hi@20992 lo@27648;
    // mid @34304 (13312B)
    {
        uint16_t* mB = (uint16_t*)(smem + 34304);
        for (int i = 0; i < 5; i++) {
            CP_WAIT0();
            __syncthreads();
            float acc[2][3][4];
            zacc<3>(acc);
            mma2<2, 3>(sb + 512, sb + 5632, sb + 13312, 40, mt * 32,
                       nt * 3, lane, acc);
            __syncthreads();
            if (i < 4) {
                cpy1(sb + 512, x + 22528 + (i + 1) * 2560, 2560);
                CP_COMMIT();
            }
#pragma unroll
            for (int m = 0; m < 2; m++) {
                const int r0 = mt * 32 + m * 16 + g;
#pragma unroll
                for (int j = 0; j < 3; j++) {
                    const int c = (nt * 3 + j) * 8 + t2 * 2;
#pragma unroll
                    for (int h2 = 0; h2 < 2; h2++) {
                        const int r = r0 + h2 * 8;
                        const float a = sAttr[r] * I12;
                        const float2 gg = *reinterpret_cast<const float2*>(
                            gate + r * 288 + 192 + c);
                        *reinterpret_cast<uint32_t*>(mB + r * 104 + c) =
                            pk16(acc[m][j][h2 * 2] * a * gg.x,
                                 acc[m][j][h2 * 2 + 1] * a * gg.y);
                    }
                }
            }
            __syncthreads();
            float acc2[2][1][4];
            zacc<1>(acc2);
            mma2<6, 1>(sb + 34304, sb + 20992, sb + 27648, 104, mt * 32,
                       nt, lane, acc2);
            __syncthreads();
#pragma unroll
            for (int m = 0; m < 2; m++) {
                const int r0 = mt * 32 + m * 16 + g;
                const int c = nt * 8 + t2 * 2;
#pragma unroll
                for (int h2 = 0; h2 < 2; h2++) {
                    const int r = r0 + h2 * 8, node = nbase + r;
                    if (node < Nn) {
                        const float a = sAttr[r] * I22;
                        out[(size_t)node * 480 + 320 + c * 5 + i] =
                            acc2[m][0][h2 * 2] * a;
                        out[(size_t)node * 480 + 320 + (c + 1) * 5 + i] =
                            acc2[m][0][h2 * 2 + 1] * a;
                    }
                }
            }
        }
    }
}

extern "C" void kernel_launch(void* const* d_in, const int* in_sizes, int n_in,
                              void* d_out, int out_size) {
    const float* X    = (const float*)d_in[0];
    const float* attr = (const float*)d_in[1];
    const float* W1_0 = (const float*)d_in[2];
    const float* W1_1 = (const float*)d_in[3];
    const float* W1_2 = (const float*)d_in[4];
    const float* b1   = (const float*)d_in[5];
    const float* W2_0 = (const float*)d_in[6];
    const float* W2_1 = (const float*)d_in[7];
    const float* W2_2 = (const float*)d_in[8];
    const float* b2   = (const float*)d_in[9];
    float* out = (float*)d_out;

    const int N = in_sizes[0] / 480;
    int nct = (N + 63) / 64;
    if (nct > MAXCTA) nct = MAXCTA;

    prep1<<<160, 256>>>(W1_0, W1_1, W1_2, W2_0, W2_1, W2_2);
    prep2<<<2048, 256>>>(X, N, nct);
    cudaFuncSetAttribute(ffn_main, cudaFuncAttributeMaxDynamicSharedMemorySize, SM_TOT);
    ffn_main<<<nct, THREADS, SM_TOT>>>(attr, b1, b2, out, N);
}

// round 16
// speedup vs baseline: 1.6478x; 1.3151x over previous
#include <cuda_runtime.h>
#include <cuda_fp16.h>
#include <cstdint>
#include <math.h>

// ============================================================================
// Equiformer FFN via mma.sync m16n8k16 fp16 single-precision-operand scheme:
// A = fp16, B = fp16 (one MMA per tile-k), fp32 accum. rel_err ~3e-4.
// CTA = 64 nodes, 256 threads (8 warps 2m x 4n), 3 CTAs/SM (50.6KB smem).
// R9/R15 phase & wait structure. X pre-converted fp16 by vectorized prep.
// ============================================================================

#define THREADS 256
#define MAXCTA  1563

// ---- pre-converted weights (fp16) ----
#define OFF10 0        // [672 n][136]   (7 chunks of 96 n, 13056 each)
#define OFF11 91392    // [192 n][72]    (2 chunks of 96 n, 6912 each)
#define OFF12 105216   // [96 n][40]
#define OFF20 109056   // 8 x [128 n][56]   (K chunks of 48)
#define OFF21 166400   // 2 x [64 n][104]   (K chunks of 96)
#define OFF22 179712   // [32 n][104]
#define WTOT  183040
__device__ __align__(16) uint16_t g_wh[WTOT];

// ---- pre-converted X (fp16) per 64-node CTA ----
#define XBLK 35328
__device__ __align__(16) uint16_t g_x[(size_t)MAXCTA * XBLK];

// scalars fp16 [64 r][392] + gates fp32 [64 r][288]
__device__ __align__(16) uint16_t g_sc[(size_t)MAXCTA * 25088];
__device__ __align__(16) float    g_gate[(size_t)MAXCTA * 18432];

#define SM_TOT 50688

__device__ __forceinline__ uint32_t s2u(const void* p) {
    uint32_t a;
    asm("{ .reg .u64 t; cvta.to.shared.u64 t, %1; cvt.u32.u64 %0, t; }" : "=r"(a) : "l"(p));
    return a;
}
__device__ __forceinline__ void ldm_x4(uint32_t d[4], uint32_t a) {
    asm volatile("ldmatrix.sync.aligned.m8n8.x4.shared.b16 {%0,%1,%2,%3}, [%4];"
                 : "=r"(d[0]), "=r"(d[1]), "=r"(d[2]), "=r"(d[3]) : "r"(a));
}
__device__ __forceinline__ void ldm_x2(uint32_t d[2], uint32_t a) {
    asm volatile("ldmatrix.sync.aligned.m8n8.x2.shared.b16 {%0,%1}, [%2];"
                 : "=r"(d[0]), "=r"(d[1]) : "r"(a));
}
__device__ __forceinline__ void mma_f16(float (&c)[4], const uint32_t (&a)[4],
                                        const uint32_t (&b)[2]) {
    asm volatile("mma.sync.aligned.m16n8k16.row.col.f32.f16.f16.f32 "
                 "{%0,%1,%2,%3},{%4,%5,%6,%7},{%8,%9},{%0,%1,%2,%3};"
                 : "+f"(c[0]), "+f"(c[1]), "+f"(c[2]), "+f"(c[3])
                 : "r"(a[0]), "r"(a[1]), "r"(a[2]), "r"(a[3]), "r"(b[0]), "r"(b[1]));
}
__device__ __forceinline__ uint32_t pk16(float v0, float v1) {
    return (uint32_t)__half_as_ushort(__float2half_rn(v0)) |
           ((uint32_t)__half_as_ushort(__float2half_rn(v1)) << 16);
}
__device__ __forceinline__ void cp16(uint32_t dst, const void* src) {
    asm volatile("cp.async.cg.shared.global [%0], [%1], 16;" :: "r"(dst), "l"(src));
}
#define CP_COMMIT() asm volatile("cp.async.commit_group;" ::: "memory")
#define CP_WAIT0()  asm volatile("cp.async.wait_group 0;" ::: "memory")
#define CP_WAIT1()  asm volatile("cp.async.wait_group 1;" ::: "memory")

__device__ __forceinline__ void cpy1(uint32_t d, const uint16_t* s, int elems) {
    const int n16 = elems >> 3;
    for (int i = threadIdx.x; i < n16; i += THREADS) cp16(d + i * 16, s + i * 8);
}
// scalars: 64 rows x 6 chunks of 16B from [r][392] col kcOff -> [r][56pad]
__device__ __forceinline__ void cpy_sc48(uint32_t d, const uint16_t* s, int kcOff) {
    for (int i = threadIdx.x; i < 384; i += THREADS) {
        const int r = i / 6, ch = i - r * 6;
        cp16(d + r * 112 + ch * 16, s + r * 392 + kcOff + ch * 8);
    }
}

template <int NTW>
__device__ __forceinline__ void zacc(float (&acc)[2][NTW][4]) {
#pragma unroll
    for (int m = 0; m < 2; m++)
#pragma unroll
        for (int j = 0; j < NTW; j++)
#pragma unroll
            for (int q = 0; q < 4; q++) acc[m][j][q] = 0.0f;
}

// single-term fp16 mma tile
template <int KT, int NTW>
__device__ __forceinline__ void mma1(uint32_t uA, uint32_t uB, int Kpad,
                                     int rowBase, int n8Base, int lane,
                                     float (&acc)[2][NTW][4]) {
    const int ar  = rowBase + (lane & 15);
    const int ak8 = (lane >> 4) * 8;
    const int bn  = lane & 7;
    const int bk8 = ((lane >> 3) & 1) * 8;
#pragma unroll 1
    for (int kt = 0; kt < KT; kt++) {
        const int kb = kt * 16;
        uint32_t A[2][4];
#pragma unroll
        for (int m = 0; m < 2; m++)
            ldm_x4(A[m], uA + (uint32_t)(((ar + m * 16) * Kpad + kb + ak8) * 2));
#pragma unroll
        for (int j = 0; j < NTW; j++) {
            uint32_t B[2];
            ldm_x2(B, uB + (uint32_t)((((n8Base + j) * 8 + bn) * Kpad + kb + bk8) * 2));
#pragma unroll
            for (int m = 0; m < 2; m++) mma_f16(acc[m][j], A[m], B);
        }
    }
}

// ---- prep1: weights -> fp16 ----
__device__ __forceinline__ void prep_w(const float* __restrict__ W, int K, int N,
                                       int Kpad, int base) {
    const int tot = K * N;
    for (int idx = blockIdx.x * blockDim.x + threadIdx.x; idx < tot;
         idx += gridDim.x * blockDim.x) {
        const int k = idx / N, n = idx - k * N;
        g_wh[base + n * Kpad + k] =
            __half_as_ushort(__float2half_rn(__ldg(&W[idx])));
    }
}
__global__ void prep1(const float* W1_0, const float* W1_1, const float* W1_2,
                      const float* W2_0, const float* W2_1, const float* W2_2) {
    prep_w(W1_0, 128, 672, 136, OFF10);
    prep_w(W1_1, 64, 192, 72, OFF11);
    prep_w(W1_2, 32, 96, 40, OFF12);
    for (int idx = blockIdx.x * blockDim.x + threadIdx.x; idx < 384 * 128;
         idx += gridDim.x * blockDim.x) {
        const int k = idx / 128, n = idx - k * 128;
        const int kc = k / 48, kk = k - kc * 48;
        g_wh[OFF20 + kc * 7168 + n * 56 + kk] =
            __half_as_ushort(__float2half_rn(__ldg(&W2_0[idx])));
    }
    for (int idx = blockIdx.x * blockDim.x + threadIdx.x; idx < 192 * 64;
         idx += gridDim.x * blockDim.x) {
        const int k = idx / 64, n = idx - k * 64;
        const int kc = k / 96, kk = k - kc * 96;
        g_wh[OFF21 + kc * 6656 + n * 104 + kk] =
            __half_as_ushort(__float2half_rn(__ldg(&W2_1[idx])));
    }
    prep_w(W2_2, 96, 32, 104, OFF22);
}

// ---- prep2: X -> fp16, vectorized 16B stores (60 units/node) ----
__global__ void prep2(const float* __restrict__ X, int Nn, int nct) {
    const int total = nct * 64 * 60;
    for (int idx = blockIdx.x * blockDim.x + threadIdx.x; idx < total;
         idx += gridDim.x * blockDim.x) {
        const int node = idx / 60, u = idx - node * 60;
        const int r = node & 63, cta = node >> 6;
        const float* p = X + (size_t)min(node, Nn - 1) * 480;
        const size_t base = (size_t)cta * XBLK;
        float v[8];
        size_t off;
        if (u < 16) {
#pragma unroll
            for (int q = 0; q < 8; q++) v[q] = __ldg(&p[u * 8 + q]);
            off = base + r * 136 + u * 8;
        } else if (u < 40) {
            const int i = (u - 16) >> 3, b = (u - 16) & 7;
#pragma unroll
            for (int q = 0; q < 8; q++) v[q] = __ldg(&p[128 + 24 * b + i + 3 * q]);
            off = base + 8704 + i * 4608 + r * 72 + b * 8;
        } else {
            const int i = (u - 40) >> 2, b = (u - 40) & 3;
#pragma unroll
            for (int q = 0; q < 8; q++) v[q] = __ldg(&p[320 + 40 * b + i + 5 * q]);
            off = base + 22528 + i * 2560 + r * 40 + b * 8;
        }
        uint4 o;
        o.x = pk16(v[0], v[1]);
        o.y = pk16(v[2], v[3]);
        o.z = pk16(v[4], v[5]);
        o.w = pk16(v[6], v[7]);
        *reinterpret_cast<uint4*>(g_x + off) = o;
    }
}

__global__ void __launch_bounds__(THREADS, 3)
ffn_main(const float* __restrict__ attr, const float* __restrict__ b1,
         const float* __restrict__ b2, float* __restrict__ out, int Nn) {
    extern __shared__ char smem[];
    float* sAttr = (float*)smem;
    const uint32_t sb = s2u(smem);
    const int tid = threadIdx.x, lane = tid & 31, w = tid >> 5;
    const int g = lane >> 2, t2 = lane & 3;
    const int mt = w >> 2, nt = w & 3;   // 2m x 4n
    const size_t cta = blockIdx.x;
    const int nbase = (int)cta * 64;
    const uint16_t* x = g_x + cta * XBLK;
    uint16_t* sc = g_sc + cta * 25088;
    float* gate = g_gate + cta * 18432;

    const float I10 = 0.08838834764831843f, I11 = 0.125f, I12 = 0.17677669529663687f;
    const float I20 = 0.05103103630798288f, I21 = 0.07216878364870323f,
                I22 = 0.10206207261596577f;

    // ===== P0: h0 = x0 @ W1_0 (7 N-chunks of 96) =====
    // A seg0 @512 (17408B); B chunk [96][136] @17920 (26112B)
    cpy1(sb + 512, x, 8704);
    cpy1(sb + 17920, g_wh + OFF10, 13056);
    CP_COMMIT();
    if (tid < 64) sAttr[tid] = attr[min(nbase + tid, Nn - 1)];
    for (int ch = 0; ch < 7; ch++) {
        CP_WAIT0();
        __syncthreads();
        float acc[2][3][4];
        zacc<3>(acc);
        mma1<8, 3>(sb + 512, sb + 17920, 136, mt * 32, nt * 3, lane, acc);
        __syncthreads();
        if (ch < 6) {
            cpy1(sb + 17920, g_wh + OFF10 + (ch + 1) * 13056, 13056);
            CP_COMMIT();
        } else {
            // prefetch P1 kc0: A scalars 0..47 @512, B W2_0 kc0 @14848
            cpy_sc48(sb + 512, sc, 0);
            cpy1(sb + 14848, g_wh + OFF20, 7168);
            CP_COMMIT();
        }
#pragma unroll
        for (int m = 0; m < 2; m++) {
            const int r0 = mt * 32 + m * 16 + g;
#pragma unroll
            for (int j = 0; j < 3; j++) {
                const int gc = ch * 96 + (nt * 3 + j) * 8 + t2 * 2;
                const float bb0 = __ldg(&b1[gc]), bb1 = __ldg(&b1[gc + 1]);
#pragma unroll
                for (int h2 = 0; h2 < 2; h2++) {
                    const int r = r0 + h2 * 8;
                    const float a = sAttr[r] * I10;
                    const float x0 = acc[m][j][h2 * 2] * a + bb0;
                    const float x1 = acc[m][j][h2 * 2 + 1] * a + bb1;
                    const float s0 = 1.0f / (1.0f + __expf(-x0));
                    const float s1 = 1.0f / (1.0f + __expf(-x1));
                    if (gc < 384)
                        *reinterpret_cast<uint32_t*>(sc + r * 392 + gc) =
                            pk16(x0 * s0, x1 * s1);
                    else
                        *reinterpret_cast<float2*>(gate + r * 288 + gc - 384) =
                            make_float2(s0, s1);
                }
            }
        }
    }

    // ===== P1: out0 = scalars @ W2_0 (8 K-chunks of 48, double-buffered) =====
    // A [64][56] @512/@7680; B [128][56] @14848/@29184
    {
        const uint32_t aB[2] = {sb + 512, sb + 7680};
        const uint32_t bB[2] = {sb + 14848, sb + 29184};
        float acc[2][4][4];
        zacc<4>(acc);
        for (int kc = 0; kc < 8; kc++) {
            const int s = kc & 1;
            if (kc < 7) {
                cpy_sc48(aB[1 - s], sc, (kc + 1) * 48);
                cpy1(bB[1 - s], g_wh + OFF20 + (kc + 1) * 7168, 7168);
                CP_COMMIT();
                CP_WAIT1();
            } else {
                CP_WAIT0();
            }
            __syncthreads();
            mma1<3, 4>(aB[s], bB[s], 56, mt * 32, nt * 4, lane, acc);
            __syncthreads();
        }
        // prefetch P2: X1_0 @512, W1_1 chunk0 @9728
        cpy1(sb + 512, x + 8704, 4608);
        cpy1(sb + 9728, g_wh + OFF11, 6912);
        CP_COMMIT();
        // out0 epilogue
#pragma unroll
        for (int m = 0; m < 2; m++) {
            const int r0 = mt * 32 + m * 16 + g;
#pragma unroll
            for (int j = 0; j < 4; j++) {
                const int c = (nt * 4 + j) * 8 + t2 * 2;
                const float bb0 = __ldg(&b2[c]), bb1 = __ldg(&b2[c + 1]);
#pragma unroll
                for (int h2 = 0; h2 < 2; h2++) {
                    const int r = r0 + h2 * 8, node = nbase + r;
                    if (node < Nn) {
                        const float a = sAttr[r] * I20;
                        *reinterpret_cast<float2*>(out + (size_t)node * 480 + c) =
                            make_float2(acc[m][j][h2 * 2] * a + bb0,
                                        acc[m][j][h2 * 2 + 1] * a + bb1);
                    }
                }
            }
        }
    }

    // ===== P2: mid1_i -> out1_i fused, K-split 96+96 (i=0..2) =====
    // X1 @512 (9216B); W1_1 @9728 (13824B); mid @23552 (13312B);
    // W2_1 @36864 (13312B)
    {
        uint16_t* mB = (uint16_t*)(smem + 23552);
        for (int i = 0; i < 3; i++) {
            float acc2[2][2][4];
            zacc<2>(acc2);
            for (int kc = 0; kc < 2; kc++) {
                CP_WAIT0();
                __syncthreads();
                float acc[2][3][4];
                zacc<3>(acc);
                mma1<4, 3>(sb + 512, sb + 9728, 72, mt * 32, nt * 3, lane, acc);
                __syncthreads();
                // group A: W2_1(kc)
                cpy1(sb + 36864, g_wh + OFF21 + kc * 6656, 6656);
                CP_COMMIT();
                // group B: next inputs
                if (kc == 0) {
                    cpy1(sb + 9728, g_wh + OFF11 + 6912, 6912);
                } else if (i < 2) {
                    cpy1(sb + 9728, g_wh + OFF11, 6912);
                    cpy1(sb + 512, x + 8704 + (i + 1) * 4608, 4608);
                } else {
                    // P3 preload into regions dead after final mid1 mma:
                    // X2_0 @512, W1_2 @5632, W2_2 @13312
                    cpy1(sb + 512, x + 22528, 2560);
                    cpy1(sb + 5632, g_wh + OFF12, 3840);
                    cpy1(sb + 13312, g_wh + OFF22, 3328);
                }
                CP_COMMIT();
                // mid epilogue -> smem fp16
#pragma unroll
                for (int m = 0; m < 2; m++) {
                    const int r0 = mt * 32 + m * 16 + g;
#pragma unroll
                    for (int j = 0; j < 3; j++) {
                        const int c = (nt * 3 + j) * 8 + t2 * 2;
#pragma unroll
                        for (int h2 = 0; h2 < 2; h2++) {
                            const int r = r0 + h2 * 8;
                            const float a = sAttr[r] * I11;
                            const float2 gg = *reinterpret_cast<const float2*>(
                                gate + r * 288 + kc * 96 + c);
                            *reinterpret_cast<uint32_t*>(mB + r * 104 + c) =
                                pk16(acc[m][j][h2 * 2] * a * gg.x,
                                     acc[m][j][h2 * 2 + 1] * a * gg.y);
                        }
                    }
                }
                __syncthreads();
                CP_WAIT1();   // W2_1(kc) landed; group B may pend
                __syncthreads();
                mma1<6, 2>(sb + 23552, sb + 36864, 104, mt * 32, nt * 2, lane, acc2);
                __syncthreads();
            }
            // out1 epilogue
#pragma unroll
            for (int m = 0; m < 2; m++) {
                const int r0 = mt * 32 + m * 16 + g;
#pragma unroll
                for (int j = 0; j < 2; j++) {
                    const int c = (nt * 2 + j) * 8 + t2 * 2;
#pragma unroll
                    for (int h2 = 0; h2 < 2; h2++) {
                        const int r = r0 + h2 * 8, node = nbase + r;
                        if (node < Nn) {
                            const float a = sAttr[r] * I21;
                            out[(size_t)node * 480 + 128 + c * 3 + i] =
                                acc2[m][j][h2 * 2] * a;
                            out[(size_t)node * 480 + 128 + (c + 1) * 3 + i] =
                                acc2[m][j][h2 * 2 + 1] * a;
                        }
                    }
                }
            }
        }
    }

    // ===== P3: mid2_i -> out2_i fused (i=0..4) =====
    // X2 @512 (5120B); W1_2 @5632 (7680B); W2_2 @13312 (6656B); mid @19968
    {
        uint16_t* mB = (uint16_t*)(smem + 19968);
        for (int i = 0; i < 5; i++) {
            CP_WAIT0();
            __syncthreads();
            float acc[2][3][4];
            zacc<3>(acc);
            mma1<2, 3>(sb + 512, sb + 5632, 40, mt * 32, nt * 3, lane, acc);
            __syncthreads();
            if (i < 4) {
                cpy1(sb + 512, x + 22528 + (i + 1) * 2560, 2560);
                CP_COMMIT();
            }
#pragma unroll
            for (int m = 0; m < 2; m++) {
                const int r0 = mt * 32 + m * 16 + g;
#pragma unroll
                for (int j = 0; j < 3; j++) {
                    const int c = (nt * 3 + j) * 8 + t2 * 2;
#pragma unroll
                    for (int h2 = 0; h2 < 2; h2++) {
                        const int r = r0 + h2 * 8;
                        const float a = sAttr[r] * I12;
                        const float2 gg = *reinterpret_cast<const float2*>(
                            gate + r * 288 + 192 + c);
                        *reinterpret_cast<uint32_t*>(mB + r * 104 + c) =
                            pk16(acc[m][j][h2 * 2] * a * gg.x,
                                 acc[m][j][h2 * 2 + 1] * a * gg.y);
                    }
                }
            }
            __syncthreads();
            float acc2[2][1][4];
            zacc<1>(acc2);
            mma1<6, 1>(sb + 19968, sb + 13312, 104, mt * 32, nt, lane, acc2);
            __syncthreads();
#pragma unroll
            for (int m = 0; m < 2; m++) {
                const int r0 = mt * 32 + m * 16 + g;
                const int c = nt * 8 + t2 * 2;
#pragma unroll
                for (int h2 = 0; h2 < 2; h2++) {
                    const int r = r0 + h2 * 8, node = nbase + r;
                    if (node < Nn) {
                        const float a = sAttr[r] * I22;
                        out[(size_t)node * 480 + 320 + c * 5 + i] =
                            acc2[m][0][h2 * 2] * a;
                        out[(size_t)node * 480 + 320 + (c + 1) * 5 + i] =
                            acc2[m][0][h2 * 2 + 1] * a;
                    }
                }
            }
        }
    }
}

extern "C" void kernel_launch(void* const* d_in, const int* in_sizes, int n_in,
                              void* d_out, int out_size) {
    const float* X    = (const float*)d_in[0];
    const float* attr = (const float*)d_in[1];
    const float* W1_0 = (const float*)d_in[2];
    const float* W1_1 = (const float*)d_in[3];
    const float* W1_2 = (const float*)d_in[4];
    const float* b1   = (const float*)d_in[5];
    const float* W2_0 = (const float*)d_in[6];
    const float* W2_1 = (const float*)d_in[7];
    const float* W2_2 = (const float*)d_in[8];
    const float* b2   = (const float*)d_in[9];
    float* out = (float*)d_out;

    const int N = in_sizes[0] / 480;
    int nct = (N + 63) / 64;
    if (nct > MAXCTA) nct = MAXCTA;

    prep1<<<160, 256>>>(W1_0, W1_1, W1_2, W2_0, W2_1, W2_2);
    prep2<<<2048, 256>>>(X, N, nct);
    cudaFuncSetAttribute(ffn_main, cudaFuncAttributeMaxDynamicSharedMemorySize, SM_TOT);
    ffn_main<<<nct, THREADS, SM_TOT>>>(attr, b1, b2, out, N);
}